// round 8
// baseline (speedup 1.0000x reference)
#include <cuda_runtime.h>
#include <cstdint>

// Problem constants (fixed by setup_inputs)
#define NB    2
#define CIN   32
#define HH    64
#define WW    64
#define LL    (HH * WW)     // 4096
#define OC    32
#define KKK   288           // C * 3 * 3
#define UNIT_ROWS 8                 // k-rows per warp-wide 1KB load
#define NCHUNK 4                    // warps interleaved per location
#define NITC  (KKK / (UNIT_ROWS * NCHUNK))   // 9 steps per warp
#define PF    2                     // 256-bit loads in flight per lane
#define LOCS_PER_BLOCK 2
#define THREADS (LOCS_PER_BLOCK * NCHUNK * 32)   // 256

struct f8 { float v0,v1,v2,v3,v4,v5,v6,v7; };

__device__ __forceinline__ f8 ldg256_cs(const float* p) {
    f8 r;
    asm volatile("ld.global.cs.v8.f32 {%0,%1,%2,%3,%4,%5,%6,%7}, [%8];"
                 : "=f"(r.v0), "=f"(r.v1), "=f"(r.v2), "=f"(r.v3),
                   "=f"(r.v4), "=f"(r.v5), "=f"(r.v6), "=f"(r.v7)
                 : "l"(p));
    return r;
}

__global__ __launch_bounds__(THREADS)
void conv_with_filter_kernel(const float* __restrict__ feat,
                             const float* __restrict__ filt,
                             float* __restrict__ out)
{
    __shared__ float sfeat[LOCS_PER_BLOCK][KKK];           // 2 x 288
    __shared__ float sacc[LOCS_PER_BLOCK][NCHUNK][OC];     // 2 x 4 x 32

    const int tid  = threadIdx.x;
    const int warp = tid >> 5;
    const int lane = tid & 31;

    const int idx0 = blockIdx.x * LOCS_PER_BLOCK;          // first location idx
    const int n    = idx0 >> 12;                           // same n for whole block
    const int lbase = idx0 & 4095;

    // ---- cooperative staging of the unfold patches (2 x 288 floats) ----
    // patch ordering k = c*9 + kh*3 + kw
    #pragma unroll
    for (int v = tid; v < LOCS_PER_BLOCK * KKK; v += THREADS) {
        const int loc = v / KKK;
        const int k   = v % KKK;
        const int c   = k / 9;
        const int r   = k % 9;
        const int kh  = r / 3;
        const int kw  = r % 3;
        const int l   = lbase + loc;
        const int hy  = (l >> 6) + kh - 1;
        const int wx  = (l & 63) + kw - 1;
        float val = 0.0f;
        if (hy >= 0 && hy < HH && wx >= 0 && wx < WW)
            val = __ldg(feat + (((size_t)n * CIN + c) * HH + hy) * WW + wx);
        sfeat[loc][k] = val;
    }
    __syncthreads();

    // ---- interleaved K streaming with 256-bit loads ----
    // unit = 8 k-rows x 32 O = 1KB per warp instruction.
    // lane: g = k-row within unit (0..7), ob = 8 O-columns (lane&3)*8.
    const int loc   = warp >> 2;        // 0..1
    const int chunk = warp & 3;         // 0..3
    const int g  = lane >> 2;           // 0..7
    const int ob = (lane & 3) * 8;      // 0,8,16,24

    const int idx = idx0 + loc;
    const float* fw = filt + (size_t)idx * (KKK * OC)
                           + (size_t)(chunk * UNIT_ROWS + g) * OC + ob;
    // step stride = NCHUNK*UNIT_ROWS*OC = 1024 floats (4KB)
    const float* s = sfeat[loc] + chunk * UNIT_ROWS + g;   // k stride 32/step

    f8 buf[PF];
    #pragma unroll
    for (int j = 0; j < PF; j++)
        buf[j] = ldg256_cs(fw + j * (NCHUNK * UNIT_ROWS * OC));

    float a0=0.f,a1=0.f,a2=0.f,a3=0.f,a4=0.f,a5=0.f,a6=0.f,a7=0.f;

    #pragma unroll
    for (int step = 0; step < NITC; step++) {
        const f8 w = buf[step % PF];
        if (step < NITC - PF)
            buf[step % PF] = ldg256_cs(fw + (size_t)(step + PF) * (NCHUNK * UNIT_ROWS * OC));
        const float f = s[step * (NCHUNK * UNIT_ROWS)];
        a0 = fmaf(f, w.v0, a0); a1 = fmaf(f, w.v1, a1);
        a2 = fmaf(f, w.v2, a2); a3 = fmaf(f, w.v3, a3);
        a4 = fmaf(f, w.v4, a4); a5 = fmaf(f, w.v5, a5);
        a6 = fmaf(f, w.v6, a6); a7 = fmaf(f, w.v7, a7);
    }

    // ---- reduce across the 8 k-row groups (lane bits 2,3,4) ----
    #pragma unroll
    for (int off = 4; off <= 16; off <<= 1) {
        a0 += __shfl_xor_sync(0xffffffffu, a0, off);
        a1 += __shfl_xor_sync(0xffffffffu, a1, off);
        a2 += __shfl_xor_sync(0xffffffffu, a2, off);
        a3 += __shfl_xor_sync(0xffffffffu, a3, off);
        a4 += __shfl_xor_sync(0xffffffffu, a4, off);
        a5 += __shfl_xor_sync(0xffffffffu, a5, off);
        a6 += __shfl_xor_sync(0xffffffffu, a6, off);
        a7 += __shfl_xor_sync(0xffffffffu, a7, off);
    }

    if (g == 0) {
        float* sa = sacc[loc][chunk] + ob;
        sa[0] = a0; sa[1] = a1; sa[2] = a2; sa[3] = a3;
        sa[4] = a4; sa[5] = a5; sa[6] = a6; sa[7] = a7;
    }
    __syncthreads();

    // ---- combine 4 chunk partials, relu, store ----
    // out layout [N, OC, L]
    if (tid < OC * LOCS_PER_BLOCK) {
        const int o  = tid >> 1;        // 0..31
        const int lc = tid & 1;         // 0..1
        float sum = sacc[lc][0][o] + sacc[lc][1][o] + sacc[lc][2][o] + sacc[lc][3][o];
        out[((size_t)n * OC + o) * LL + lbase + lc] = fmaxf(sum, 0.f);
    }
}

extern "C" void kernel_launch(void* const* d_in, const int* in_sizes, int n_in,
                              void* d_out, int out_size)
{
    const float* feat = (const float*)d_in[0];                 // [2,32,64,64]
    const float* filt = (const float*)d_in[1];                 // [2,4096,288,32]
    float*       out  = (float*)d_out;                         // [2,32,64,64]

    const int blocks = NB * LL / LOCS_PER_BLOCK;               // 4096
    conv_with_filter_kernel<<<blocks, THREADS>>>(feat, filt, out);
}

// round 9
// speedup vs baseline: 1.0368x; 1.0368x over previous
#include <cuda_runtime.h>
#include <cstdint>

// Problem constants (fixed by setup_inputs)
#define NB    2
#define CIN   32
#define HH    64
#define WW    64
#define LL    (HH * WW)     // 4096
#define OC    32
#define KKK   288           // C * 3 * 3
#define NCHUNK 4                    // K-split per location (contiguous chunks)
#define KC    (KKK / NCHUNK)        // 72 k-rows per chunk
#define NITC  (KC / 4)              // 18 pipeline steps per chunk
#define PF    4                     // loads in flight per lane
#define LOCS_PER_BLOCK 2
#define THREADS (LOCS_PER_BLOCK * NCHUNK * 32)   // 256

__global__ __launch_bounds__(THREADS, 7)
void conv_with_filter_kernel(const float* __restrict__ feat,
                             const float4* __restrict__ filt,
                             float* __restrict__ out)
{
    __shared__ float sfeat[LOCS_PER_BLOCK][KKK];           // 2 x 288
    __shared__ float sacc[LOCS_PER_BLOCK][NCHUNK][OC];     // 2 x 4 x 32

    const int tid  = threadIdx.x;
    const int warp = tid >> 5;
    const int lane = tid & 31;

    const int idx0 = blockIdx.x * LOCS_PER_BLOCK;          // first location idx
    const int n    = idx0 >> 12;                           // same n for whole block
    const int lbase = idx0 & 4095;

    const int loc   = warp >> 2;        // 0..1
    const int chunk = warp & 3;         // 0..3
    const int g  = lane >> 3;           // k-row within group of 4
    const int o4 = lane & 7;            // float4 column (8 cols = 32 outputs)

    const int idx    = idx0 + loc;
    const int l      = lbase + loc;
    const int kstart = chunk * KC;

    // ---- issue filter prefetches FIRST (nothing depends on sfeat yet) ----
    const float4* fw = filt + (size_t)idx * (KKK * OC / 4)
                            + (size_t)(kstart + g) * (OC / 4) + o4;
    float4 buf[PF];
    #pragma unroll
    for (int j = 0; j < PF; j++)
        buf[j] = __ldcs(fw + j * 32);

    // ---- per-warp feature staging (only this warp's 72-float slice) ----
    // patch ordering k = c*9 + kh*3 + kw; slice [kstart, kstart+KC)
    {
        const int hh = l >> 6;
        const int ww = l & 63;
        #pragma unroll
        for (int j = 0; j < 3; j++) {
            const int k = kstart + j * 32 + lane;   // KC = 72 = 32+32+8
            if (j < 2 || lane < 8) {
                const int c  = k / 9;
                const int r  = k % 9;
                const int hy = hh + (r / 3) - 1;
                const int wx = ww + (r % 3) - 1;
                float val = 0.0f;
                if (hy >= 0 && hy < HH && wx >= 0 && wx < WW)
                    val = __ldg(feat + (((size_t)n * CIN + c) * HH + hy) * WW + wx);
                sfeat[loc][k] = val;
            }
        }
        __syncwarp();
    }

    const float* s = sfeat[loc] + kstart + g;

    // ---- stream this warp's 72-row contiguous chunk ----
    float4 acc = make_float4(0.f, 0.f, 0.f, 0.f);

    #pragma unroll
    for (int step = 0; step < NITC; step++) {
        const float4 w4 = buf[step % PF];
        if (step < NITC - PF)
            buf[step % PF] = __ldcs(fw + (step + PF) * 32);
        const float f = s[step * 4];
        acc.x = fmaf(f, w4.x, acc.x);
        acc.y = fmaf(f, w4.y, acc.y);
        acc.z = fmaf(f, w4.z, acc.z);
        acc.w = fmaf(f, w4.w, acc.w);
    }

    // ---- reduce across the 4 k-row groups within the warp ----
    #pragma unroll
    for (int off = 8; off <= 16; off <<= 1) {
        acc.x += __shfl_xor_sync(0xffffffffu, acc.x, off);
        acc.y += __shfl_xor_sync(0xffffffffu, acc.y, off);
        acc.z += __shfl_xor_sync(0xffffffffu, acc.z, off);
        acc.w += __shfl_xor_sync(0xffffffffu, acc.w, off);
    }

    if (g == 0) {
        float4* sa = reinterpret_cast<float4*>(sacc[loc][chunk]);
        sa[o4] = acc;
    }
    __syncthreads();

    // ---- combine 4 chunk partials, relu, store ----
    // out layout [N, OC, L]
    if (tid < OC * LOCS_PER_BLOCK) {
        const int o  = tid >> 1;        // 0..31
        const int lc = tid & 1;         // 0..1
        float sum = sacc[lc][0][o] + sacc[lc][1][o] + sacc[lc][2][o] + sacc[lc][3][o];
        out[((size_t)n * OC + o) * LL + lbase + lc] = fmaxf(sum, 0.f);
    }
}

extern "C" void kernel_launch(void* const* d_in, const int* in_sizes, int n_in,
                              void* d_out, int out_size)
{
    const float*  feat = (const float*)d_in[0];                // [2,32,64,64]
    const float4* filt = (const float4*)d_in[1];               // [2,4096,288,32]
    float*        out  = (float*)d_out;                        // [2,32,64,64]

    const int blocks = NB * LL / LOCS_PER_BLOCK;               // 4096
    conv_with_filter_kernel<<<blocks, THREADS>>>(feat, filt, out);
}